// round 1
// baseline (speedup 1.0000x reference)
#include <cuda_runtime.h>
#include <cstdint>
#include <cstddef>

#define B_TOT 32768
#define D_IN  128
#define A_DIM 16
#define H1D   600
#define H2D   500

#define BM 64
#define BN 64
#define BK 16

// Scratch for h1 activations: 32768 x 600 f32 = 78.6 MB (device global; no allocs).
__device__ float g_h1[(size_t)B_TOT * H1D];

__global__ __launch_bounds__(256) void init_out_kernel(const int* __restrict__ idx,
                                                       const float* __restrict__ b3,
                                                       float* __restrict__ out) {
    int i = blockIdx.x * 256 + threadIdx.x;
    if (i < B_TOT) out[i] = b3[idx[i]];
}

// h1[b, n] = relu( state[b, :] . W1[idx[b], n, :] + b1[idx[b], n] )
__global__ __launch_bounds__(256) void h1_kernel(const float* __restrict__ state,
                                                 const int* __restrict__ idx,
                                                 const float* __restrict__ W1,
                                                 const float* __restrict__ b1) {
    __shared__ __align__(16) float As[BK][BM + 4];
    __shared__ __align__(16) float Bs[BK][BN + 4];
    __shared__ int sidx[BM];
    const int tid = threadIdx.x;
    const int n0 = blockIdx.x * BN;
    const int b0 = blockIdx.y * BM;
    const int g0 = idx[b0];
    int myg = g0;
    if (tid < BM) { myg = idx[b0 + tid]; sidx[tid] = myg; }
    const bool uni = (__syncthreads_and(myg == g0) != 0);
    const int tx = tid & 15;
    const int ty = tid >> 4;

    if (uni) {
        // fast path: whole 64-sample tile belongs to one game
        const float* __restrict__ Wg  = W1 + (size_t)g0 * H1D * D_IN;
        const float* __restrict__ b1g = b1 + (size_t)g0 * H1D;
        float acc[4][4];
        #pragma unroll
        for (int i = 0; i < 4; i++)
            #pragma unroll
            for (int j = 0; j < 4; j++) acc[i][j] = 0.f;

        const int lrow = tid >> 2;        // 0..63
        const int lko  = (tid & 3) * 4;   // 0,4,8,12
        for (int k0 = 0; k0 < D_IN; k0 += BK) {
            float4 va = *(const float4*)(state + (size_t)(b0 + lrow) * D_IN + k0 + lko);
            As[lko + 0][lrow] = va.x;
            As[lko + 1][lrow] = va.y;
            As[lko + 2][lrow] = va.z;
            As[lko + 3][lrow] = va.w;
            float4 vb = make_float4(0.f, 0.f, 0.f, 0.f);
            const int n = n0 + lrow;
            if (n < H1D) vb = *(const float4*)(Wg + (size_t)n * D_IN + k0 + lko);
            Bs[lko + 0][lrow] = vb.x;
            Bs[lko + 1][lrow] = vb.y;
            Bs[lko + 2][lrow] = vb.z;
            Bs[lko + 3][lrow] = vb.w;
            __syncthreads();
            #pragma unroll
            for (int kk = 0; kk < BK; kk++) {
                float4 a4 = *(const float4*)&As[kk][ty * 4];
                float4 b4 = *(const float4*)&Bs[kk][tx * 4];
                const float av[4] = {a4.x, a4.y, a4.z, a4.w};
                const float bv[4] = {b4.x, b4.y, b4.z, b4.w};
                #pragma unroll
                for (int i = 0; i < 4; i++)
                    #pragma unroll
                    for (int j = 0; j < 4; j++)
                        acc[i][j] += av[i] * bv[j];
            }
            __syncthreads();
        }
        const int nb = n0 + tx * 4;
        if (nb < H1D) {
            #pragma unroll
            for (int i = 0; i < 4; i++) {
                const int b = b0 + ty * 4 + i;
                float4 o;
                o.x = fmaxf(acc[i][0] + b1g[nb + 0], 0.f);
                o.y = fmaxf(acc[i][1] + b1g[nb + 1], 0.f);
                o.z = fmaxf(acc[i][2] + b1g[nb + 2], 0.f);
                o.w = fmaxf(acc[i][3] + b1g[nb + 3], 0.f);
                *(float4*)(g_h1 + (size_t)b * H1D + nb) = o;
            }
        }
    } else {
        // rare boundary tile (<= 7 of 512 b-tiles): per-sample game index, global W1 reads
        const int nb = n0 + tx * 4;
        for (int i = 0; i < 4; i++) {
            const int bl = ty * 4 + i;
            const int b  = b0 + bl;
            const int g  = sidx[bl];
            const float* __restrict__ Wg  = W1 + (size_t)g * H1D * D_IN;
            const float* __restrict__ b1g = b1 + (size_t)g * H1D;
            if (nb < H1D) {
                float acc[4] = {0.f, 0.f, 0.f, 0.f};
                for (int k = 0; k < D_IN; k++) {
                    const float sv = state[(size_t)b * D_IN + k];
                    #pragma unroll
                    for (int j = 0; j < 4; j++)
                        acc[j] += sv * Wg[(size_t)(nb + j) * D_IN + k];
                }
                float4 o;
                o.x = fmaxf(acc[0] + b1g[nb + 0], 0.f);
                o.y = fmaxf(acc[1] + b1g[nb + 1], 0.f);
                o.z = fmaxf(acc[2] + b1g[nb + 2], 0.f);
                o.w = fmaxf(acc[3] + b1g[nb + 3], 0.f);
                *(float4*)(g_h1 + (size_t)b * H1D + nb) = o;
            }
        }
    }
}

// h2[b,n] = h1[b,:].W2s[n,:] + b2s[n] + action[b,:].W2a[g,n,:] ; relu ; q += h2*W3[g,n]
__global__ __launch_bounds__(256) void h2q_kernel(const float* __restrict__ action,
                                                  const int* __restrict__ idx,
                                                  const float* __restrict__ W2s,
                                                  const float* __restrict__ b2s,
                                                  const float* __restrict__ W2a,
                                                  const float* __restrict__ W3,
                                                  float* __restrict__ out) {
    __shared__ __align__(16) float As[BK][BM + 4];
    __shared__ __align__(16) float Bs[BK][BN + 4];
    __shared__ __align__(16) float Act[BM][A_DIM];
    __shared__ int sidx[BM];
    const int tid = threadIdx.x;
    const int n0 = blockIdx.x * BN;
    const int b0 = blockIdx.y * BM;
    if (tid < BM) sidx[tid] = idx[b0 + tid];
    {
        const int row = tid >> 2;
        const int vo  = (tid & 3) * 4;
        *(float4*)&Act[row][vo] = *(const float4*)(action + (size_t)(b0 + row) * A_DIM + vo);
    }
    __syncthreads();

    float acc[4][4];
    #pragma unroll
    for (int i = 0; i < 4; i++)
        #pragma unroll
        for (int j = 0; j < 4; j++) acc[i][j] = 0.f;

    const int tx = tid & 15;
    const int ty = tid >> 4;
    const int lrow = tid >> 2;
    const int lko  = (tid & 3) * 4;

    for (int k0 = 0; k0 < H1D; k0 += BK) {
        float4 va = make_float4(0.f, 0.f, 0.f, 0.f);
        if (k0 + lko < H1D)
            va = *(const float4*)(g_h1 + (size_t)(b0 + lrow) * H1D + k0 + lko);
        As[lko + 0][lrow] = va.x;
        As[lko + 1][lrow] = va.y;
        As[lko + 2][lrow] = va.z;
        As[lko + 3][lrow] = va.w;
        float4 vb = make_float4(0.f, 0.f, 0.f, 0.f);
        const int n = n0 + lrow;
        if (n < H2D && k0 + lko < H1D)
            vb = *(const float4*)(W2s + (size_t)n * H1D + k0 + lko);
        Bs[lko + 0][lrow] = vb.x;
        Bs[lko + 1][lrow] = vb.y;
        Bs[lko + 2][lrow] = vb.z;
        Bs[lko + 3][lrow] = vb.w;
        __syncthreads();
        #pragma unroll
        for (int kk = 0; kk < BK; kk++) {
            float4 a4 = *(const float4*)&As[kk][ty * 4];
            float4 b4 = *(const float4*)&Bs[kk][tx * 4];
            const float av[4] = {a4.x, a4.y, a4.z, a4.w};
            const float bv[4] = {b4.x, b4.y, b4.z, b4.w};
            #pragma unroll
            for (int i = 0; i < 4; i++)
                #pragma unroll
                for (int j = 0; j < 4; j++)
                    acc[i][j] += av[i] * bv[j];
        }
        __syncthreads();
    }

    // fused epilogue: + b2s + action GEMV, relu, dot with W3, reduce, accumulate q
    #pragma unroll
    for (int i = 0; i < 4; i++) {
        const int bl = ty * 4 + i;
        const int b  = b0 + bl;
        const int g  = sidx[bl];
        const float* __restrict__ W2ag = W2a + (size_t)g * H2D * A_DIM;
        const float* __restrict__ W3g  = W3 + (size_t)g * H2D;
        float act[A_DIM];
        #pragma unroll
        for (int a = 0; a < A_DIM; a++) act[a] = Act[bl][a];
        float qp = 0.f;
        #pragma unroll
        for (int c = 0; c < 4; c++) {
            const int n = n0 + tx * 4 + c;
            if (n < H2D) {
                const float4* wa = (const float4*)(W2ag + (size_t)n * A_DIM);
                float h2a = 0.f;
                #pragma unroll
                for (int v = 0; v < 4; v++) {
                    const float4 w4 = wa[v];
                    h2a += act[v * 4 + 0] * w4.x + act[v * 4 + 1] * w4.y +
                           act[v * 4 + 2] * w4.z + act[v * 4 + 3] * w4.w;
                }
                float val = acc[i][c] + b2s[n] + h2a;
                val = fmaxf(val, 0.f);
                qp += val * W3g[n];
            }
        }
        // reduce across the 16 column-threads of this row (lanes stay in 16-lane groups)
        qp += __shfl_xor_sync(0xffffffffu, qp, 8, 16);
        qp += __shfl_xor_sync(0xffffffffu, qp, 4, 16);
        qp += __shfl_xor_sync(0xffffffffu, qp, 2, 16);
        qp += __shfl_xor_sync(0xffffffffu, qp, 1, 16);
        if (tx == 0) atomicAdd(&out[b], qp);
    }
}

extern "C" void kernel_launch(void* const* d_in, const int* in_sizes, int n_in,
                              void* d_out, int out_size) {
    const float* state  = (const float*)d_in[0];
    const float* action = (const float*)d_in[1];
    const int*   idx    = (const int*)d_in[2];
    const float* W1     = (const float*)d_in[3];
    const float* b1     = (const float*)d_in[4];
    const float* W2s    = (const float*)d_in[5];
    const float* b2s    = (const float*)d_in[6];
    const float* W2a    = (const float*)d_in[7];
    const float* W3     = (const float*)d_in[8];
    const float* b3     = (const float*)d_in[9];
    float* out = (float*)d_out;

    init_out_kernel<<<(B_TOT + 255) / 256, 256>>>(idx, b3, out);
    h1_kernel<<<dim3((H1D + BN - 1) / BN, B_TOT / BM), 256>>>(state, idx, W1, b1);
    h2q_kernel<<<dim3((H2D + BN - 1) / BN, B_TOT / BM), 256>>>(action, idx, W2s, b2s, W2a, W3, out);
}

// round 3
// speedup vs baseline: 3.2321x; 3.2321x over previous
#include <cuda_runtime.h>
#include <cuda_bf16.h>
#include <cstdint>
#include <cstddef>

#define B_TOT 32768
#define D_IN  128
#define A_DIM 16
#define H1D   600
#define H2D   500
#define KP    640   // padded K for gemm2: 600 h1 + 16 action + 24 zero
#define PADW  136   // padded smem row width in bf16 elems (272 bytes, conflict-free ldmatrix)

// h1 activations stored as bf16 hi/lo pair, padded layout [B][KP]
__device__ __nv_bfloat16 g_h1hi[(size_t)B_TOT * KP];
__device__ __nv_bfloat16 g_h1lo[(size_t)B_TOT * KP];

// ---------------- helpers ----------------
__device__ __forceinline__ uint32_t smem_u32(const void* p) {
    uint32_t a;
    asm("{ .reg .u64 t; cvta.to.shared.u64 t, %1; cvt.u32.u64 %0, t; }" : "=r"(a) : "l"(p));
    return a;
}
__device__ __forceinline__ void ldm_x4(uint32_t* r, uint32_t addr) {
    asm volatile("ldmatrix.sync.aligned.m8n8.x4.shared.b16 {%0,%1,%2,%3}, [%4];"
                 : "=r"(r[0]), "=r"(r[1]), "=r"(r[2]), "=r"(r[3]) : "r"(addr));
}
__device__ __forceinline__ void mma16816(float* c, const uint32_t* a, const uint32_t* b) {
    asm volatile("mma.sync.aligned.m16n8k16.row.col.f32.bf16.bf16.f32 "
                 "{%0,%1,%2,%3}, {%4,%5,%6,%7}, {%8,%9}, {%0,%1,%2,%3};"
                 : "+f"(c[0]), "+f"(c[1]), "+f"(c[2]), "+f"(c[3])
                 : "r"(a[0]), "r"(a[1]), "r"(a[2]), "r"(a[3]), "r"(b[0]), "r"(b[1]));
}
__device__ __forceinline__ void cp16(uint32_t dst, const void* src) {
    asm volatile("cp.async.cg.shared.global [%0], [%1], 16;" :: "r"(dst), "l"(src) : "memory");
}
__device__ __forceinline__ void cp_commit_wait() {
    asm volatile("cp.async.commit_group;" ::: "memory");
    asm volatile("cp.async.wait_group 0;" ::: "memory");
}

// pack f0 -> low half, f1 -> high half
__device__ __forceinline__ uint32_t pack2(float f0, float f1) {
    uint32_t r;
    asm("cvt.rn.bf16x2.f32 %0, %1, %2;" : "=r"(r) : "f"(f1), "f"(f0));
    return r;
}
// split pair into bf16 hi word + bf16 lo (residual) word
__device__ __forceinline__ void split2(float f0, float f1, uint32_t& h, uint32_t& l) {
    h = pack2(f0, f1);
    float h0 = __uint_as_float(h << 16);
    float h1 = __uint_as_float(h & 0xffff0000u);
    l = pack2(f0 - h0, f1 - h1);
}
__device__ __forceinline__ void split8(float4 v0, float4 v1, uint4& H, uint4& L) {
    split2(v0.x, v0.y, H.x, L.x);
    split2(v0.z, v0.w, H.y, L.y);
    split2(v1.x, v1.y, H.z, L.z);
    split2(v1.z, v1.w, H.w, L.w);
}

// ---------------- small kernels ----------------
__global__ __launch_bounds__(256) void init_out_kernel(const int* __restrict__ idx,
                                                       const float* __restrict__ b3,
                                                       float* __restrict__ out) {
    int i = blockIdx.x * 256 + threadIdx.x;
    if (i < B_TOT) out[i] = b3[idx[i]];
}

// fill padded columns of g_h1: cols 600..615 = action hi/lo, 616..639 = zero
__global__ __launch_bounds__(256) void fill_pad_kernel(const float* __restrict__ action) {
    int b = blockIdx.x * 256 + threadIdx.x;
    if (b >= B_TOT) return;
    const float4* a4 = (const float4*)(action + (size_t)b * A_DIM);
    float4 v0 = a4[0], v1 = a4[1], v2 = a4[2], v3 = a4[3];
    uint4 H0, L0, H1, L1;
    split8(v0, v1, H0, L0);
    split8(v2, v3, H1, L1);
    uint16_t* ph = (uint16_t*)g_h1hi + (size_t)b * KP + 600;
    uint16_t* pl = (uint16_t*)g_h1lo + (size_t)b * KP + 600;
    ((uint4*)ph)[0] = H0; ((uint4*)ph)[1] = H1;
    ((uint4*)pl)[0] = L0; ((uint4*)pl)[1] = L1;
    uint4 z = make_uint4(0, 0, 0, 0);
    uint4* zh = (uint4*)(ph + 16);
    uint4* zl = (uint4*)(pl + 16);
    zh[0] = z; zh[1] = z; zh[2] = z;
    zl[0] = z; zl[1] = z; zl[2] = z;
}

// ---------------- GEMM1: h1 = relu(state . W1[g]^T + b1[g]) ----------------
// CTA tile M=128 x N=64, K=128. 8 warps as 4(m) x 2(n), warp tile 32x32.
#define SM1_BYTES (2*128*PADW*2 + 2*64*PADW*2 + 64*4 + 128*4)
__global__ __launch_bounds__(256, 2) void h1_mma_kernel(const float* __restrict__ state,
                                                        const int* __restrict__ idx,
                                                        const float* __restrict__ W1,
                                                        const float* __restrict__ b1) {
    extern __shared__ char dsm[];
    __nv_bfloat16* Ah = (__nv_bfloat16*)dsm;
    __nv_bfloat16* Al = Ah + 128 * PADW;
    __nv_bfloat16* Bh = Al + 128 * PADW;
    __nv_bfloat16* Bl = Bh + 64 * PADW;
    float* sb1 = (float*)(Bl + 64 * PADW);
    int* sidx = (int*)(sb1 + 64);

    const int tid = threadIdx.x;
    const int lane = tid & 31;
    const int wid = tid >> 5;
    const int n0 = blockIdx.x * 64;
    const int b0 = blockIdx.y * 128;

    if (tid < 128) sidx[tid] = idx[b0 + tid];

    // load state -> split -> smem (once)
    #pragma unroll
    for (int i = 0; i < 16; i++) {
        int bid = tid + i * 256;
        int row = bid >> 5, q = bid & 31;
        float4 v = *(const float4*)(state + (size_t)(b0 + row) * D_IN + q * 4);
        uint32_t h0, l0, h1, l1;
        split2(v.x, v.y, h0, l0);
        split2(v.z, v.w, h1, l1);
        uint32_t* ph = (uint32_t*)(Ah + row * PADW + q * 4);
        uint32_t* pl = (uint32_t*)(Al + row * PADW + q * 4);
        ph[0] = h0; ph[1] = h1;
        pl[0] = l0; pl[1] = l1;
    }
    __syncthreads();
    const int g_lo = sidx[0], g_hi = sidx[127];

    const uint32_t sAh = smem_u32(Ah), sAl = smem_u32(Al);
    const uint32_t sBh = smem_u32(Bh), sBl = smem_u32(Bl);
    const int m_base = (wid >> 1) * 32;
    const int n_base = (wid & 1) * 32;
    const uint32_t aoff = (uint32_t)(m_base + (lane & 15)) * 272u + (uint32_t)((lane >> 4) * 16);
    const uint32_t boff = (uint32_t)(n_base + (lane & 15)) * 272u + (uint32_t)((lane >> 4) * 16);

    for (int g = g_lo; g <= g_hi; ++g) {
        const float* __restrict__ Wg = W1 + (size_t)g * H1D * D_IN;
        #pragma unroll
        for (int i = 0; i < 8; i++) {
            int bid = tid + i * 256;
            int row = bid >> 5, q = bid & 31;
            int n = n0 + row;
            float4 v = make_float4(0.f, 0.f, 0.f, 0.f);
            if (n < H1D) v = *(const float4*)(Wg + (size_t)n * D_IN + q * 4);
            uint32_t h0, l0, h1, l1;
            split2(v.x, v.y, h0, l0);
            split2(v.z, v.w, h1, l1);
            uint32_t* ph = (uint32_t*)(Bh + row * PADW + q * 4);
            uint32_t* pl = (uint32_t*)(Bl + row * PADW + q * 4);
            ph[0] = h0; ph[1] = h1;
            pl[0] = l0; pl[1] = l1;
        }
        if (tid < 64) {
            int n = n0 + tid;
            sb1[tid] = (n < H1D) ? b1[(size_t)g * H1D + n] : 0.f;
        }
        __syncthreads();

        float C[2][4][4];
        #pragma unroll
        for (int mf = 0; mf < 2; mf++)
            #pragma unroll
            for (int nf = 0; nf < 4; nf++)
                #pragma unroll
                for (int e = 0; e < 4; e++) C[mf][nf][e] = 0.f;

        #pragma unroll
        for (int kk = 0; kk < 8; kk++) {
            uint32_t ah[2][4], al[2][4], bh[4][2], bl[4][2];
            #pragma unroll
            for (int mf = 0; mf < 2; mf++) {
                ldm_x4(ah[mf], sAh + aoff + mf * 4352u + kk * 32u);
                ldm_x4(al[mf], sAl + aoff + mf * 4352u + kk * 32u);
            }
            #pragma unroll
            for (int nq = 0; nq < 2; nq++) {
                uint32_t t[4];
                ldm_x4(t, sBh + boff + nq * 4352u + kk * 32u);
                bh[nq * 2][0] = t[0]; bh[nq * 2][1] = t[2];
                bh[nq * 2 + 1][0] = t[1]; bh[nq * 2 + 1][1] = t[3];
                ldm_x4(t, sBl + boff + nq * 4352u + kk * 32u);
                bl[nq * 2][0] = t[0]; bl[nq * 2][1] = t[2];
                bl[nq * 2 + 1][0] = t[1]; bl[nq * 2 + 1][1] = t[3];
            }
            #pragma unroll
            for (int mf = 0; mf < 2; mf++)
                #pragma unroll
                for (int nf = 0; nf < 4; nf++) {
                    mma16816(C[mf][nf], ah[mf], bh[nf]);
                    mma16816(C[mf][nf], ah[mf], bl[nf]);
                    mma16816(C[mf][nf], al[mf], bh[nf]);
                }
        }

        // epilogue: +b1, relu, split, store hi/lo where row belongs to g
        #pragma unroll
        for (int mf = 0; mf < 2; mf++)
            #pragma unroll
            for (int half = 0; half < 2; half++) {
                int r = m_base + mf * 16 + (lane >> 2) + half * 8;
                if (sidx[r] == g) {
                    size_t base = (size_t)(b0 + r) * KP;
                    #pragma unroll
                    for (int nf = 0; nf < 4; nf++) {
                        int lc = n_base + nf * 8 + 2 * (lane & 3);
                        int n = n0 + lc;
                        if (n < H1D) {
                            float v0 = fmaxf(C[mf][nf][half * 2 + 0] + sb1[lc], 0.f);
                            float v1 = fmaxf(C[mf][nf][half * 2 + 1] + sb1[lc + 1], 0.f);
                            uint32_t h, l;
                            split2(v0, v1, h, l);
                            *(uint32_t*)(g_h1hi + base + n) = h;
                            *(uint32_t*)(g_h1lo + base + n) = l;
                        }
                    }
                }
            }
        __syncthreads();
    }
}

// ---------------- GEMM2 fused: q += relu([h1|act|0].[W2s|W2a|0]^T + b2s) . W3[g] ----------
// CTA tile M=128 x N=64, K=640 in 5 chunks of 128. A via cp.async (bf16 copy).
#define SM2_BYTES (2*128*PADW*2 + 2*64*PADW*2 + 64*4 + 64*4 + 128*4)
__global__ __launch_bounds__(256, 2) void h2q_mma_kernel(const int* __restrict__ idx,
                                                         const float* __restrict__ W2s,
                                                         const float* __restrict__ b2s,
                                                         const float* __restrict__ W2a,
                                                         const float* __restrict__ W3,
                                                         float* __restrict__ out) {
    extern __shared__ char dsm[];
    __nv_bfloat16* Ah = (__nv_bfloat16*)dsm;
    __nv_bfloat16* Al = Ah + 128 * PADW;
    __nv_bfloat16* Bh = Al + 128 * PADW;
    __nv_bfloat16* Bl = Bh + 64 * PADW;
    float* sb2 = (float*)(Bl + 64 * PADW);
    float* sw3 = sb2 + 64;
    int* sidx = (int*)(sw3 + 64);

    const int tid = threadIdx.x;
    const int lane = tid & 31;
    const int wid = tid >> 5;
    const int n0 = blockIdx.x * 64;
    const int b0 = blockIdx.y * 128;

    if (tid < 128) sidx[tid] = idx[b0 + tid];
    if (tid < 64) {
        int n = n0 + tid;
        sb2[tid] = (n < H2D) ? b2s[n] : 0.f;
    }
    __syncthreads();
    const int g_lo = sidx[0], g_hi = sidx[127];

    const uint32_t sAh = smem_u32(Ah), sAl = smem_u32(Al);
    const uint32_t sBh = smem_u32(Bh), sBl = smem_u32(Bl);
    const int m_base = (wid >> 1) * 32;
    const int n_base = (wid & 1) * 32;
    const uint32_t aoff = (uint32_t)(m_base + (lane & 15)) * 272u + (uint32_t)((lane >> 4) * 16);
    const uint32_t boff = (uint32_t)(n_base + (lane & 15)) * 272u + (uint32_t)((lane >> 4) * 16);

    for (int g = g_lo; g <= g_hi; ++g) {
        if (tid < 64) {
            int n = n0 + tid;
            sw3[tid] = (n < H2D) ? W3[(size_t)g * H2D + n] : 0.f;
        }
        float C[2][4][4];
        #pragma unroll
        for (int mf = 0; mf < 2; mf++)
            #pragma unroll
            for (int nf = 0; nf < 4; nf++)
                #pragma unroll
                for (int e = 0; e < 4; e++) C[mf][nf][e] = 0.f;

        for (int kc = 0; kc < 5; ++kc) {
            // prefetch B (W2s) into regs for kc<4 while prior mma drains
            float4 u0[4], u1[4];
            if (kc < 4) {
                #pragma unroll
                for (int i = 0; i < 4; i++) {
                    int bid = tid + i * 256;
                    int row = bid >> 4, blk = bid & 15;
                    int n = n0 + row;
                    u0[i] = make_float4(0.f, 0.f, 0.f, 0.f);
                    u1[i] = u0[i];
                    if (n < H2D) {
                        const float4* gp = (const float4*)(W2s + (size_t)n * H1D + kc * 128 + blk * 8);
                        u0[i] = gp[0];
                        u1[i] = gp[1];
                    }
                }
            }
            __syncthreads();  // all warps done with prev chunk smem

            // A via cp.async: 4096 x 16B from g_h1 hi/lo
            #pragma unroll
            for (int i = 0; i < 16; i++) {
                int bid = tid + i * 256;
                int arr = bid >> 11, rem = bid & 2047;
                int row = rem >> 4, q = rem & 15;
                const __nv_bfloat16* src = (arr ? g_h1lo : g_h1hi)
                                         + (size_t)(b0 + row) * KP + kc * 128 + q * 8;
                cp16((arr ? sAl : sAh) + (uint32_t)row * 272u + (uint32_t)q * 16u, src);
            }

            // B: split+STS
            if (kc < 4) {
                #pragma unroll
                for (int i = 0; i < 4; i++) {
                    int bid = tid + i * 256;
                    int row = bid >> 4, blk = bid & 15;
                    uint4 H, L;
                    split8(u0[i], u1[i], H, L);
                    *(uint4*)(Bh + row * PADW + blk * 8) = H;
                    *(uint4*)(Bl + row * PADW + blk * 8) = L;
                }
            } else {
                // cols 512..599 = W2s tail, 600..615 = W2a[g], 616..639 = 0
                #pragma unroll 4
                for (int j = 0; j < 32; j++) {
                    int bid = tid + j * 256;
                    int row = bid >> 7, col = bid & 127;
                    int n = n0 + row;
                    int c = 512 + col;
                    float x = 0.f;
                    if (n < H2D) {
                        if (c < H1D) x = W2s[(size_t)n * H1D + c];
                        else if (c < H1D + A_DIM) x = W2a[((size_t)g * H2D + n) * A_DIM + (c - H1D)];
                    }
                    __nv_bfloat16 hb = __float2bfloat16(x);
                    __nv_bfloat16 lb = __float2bfloat16(x - __bfloat162float(hb));
                    Bh[row * PADW + col] = hb;
                    Bl[row * PADW + col] = lb;
                }
            }
            cp_commit_wait();
            __syncthreads();

            #pragma unroll
            for (int kk = 0; kk < 8; kk++) {
                uint32_t ah[2][4], al[2][4], bh[4][2], bl[4][2];
                #pragma unroll
                for (int mf = 0; mf < 2; mf++) {
                    ldm_x4(ah[mf], sAh + aoff + mf * 4352u + kk * 32u);
                    ldm_x4(al[mf], sAl + aoff + mf * 4352u + kk * 32u);
                }
                #pragma unroll
                for (int nq = 0; nq < 2; nq++) {
                    uint32_t t[4];
                    ldm_x4(t, sBh + boff + nq * 4352u + kk * 32u);
                    bh[nq * 2][0] = t[0]; bh[nq * 2][1] = t[2];
                    bh[nq * 2 + 1][0] = t[1]; bh[nq * 2 + 1][1] = t[3];
                    ldm_x4(t, sBl + boff + nq * 4352u + kk * 32u);
                    bl[nq * 2][0] = t[0]; bl[nq * 2][1] = t[2];
                    bl[nq * 2 + 1][0] = t[1]; bl[nq * 2 + 1][1] = t[3];
                }
                #pragma unroll
                for (int mf = 0; mf < 2; mf++)
                    #pragma unroll
                    for (int nf = 0; nf < 4; nf++) {
                        mma16816(C[mf][nf], ah[mf], bh[nf]);
                        mma16816(C[mf][nf], ah[mf], bl[nf]);
                        mma16816(C[mf][nf], al[mf], bh[nf]);
                    }
            }
        }

        // epilogue: relu(+b2s) . W3, quad-reduce, atomicAdd
        #pragma unroll
        for (int mf = 0; mf < 2; mf++)
            #pragma unroll
            for (int half = 0; half < 2; half++) {
                int r = m_base + mf * 16 + (lane >> 2) + half * 8;
                float qp = 0.f;
                #pragma unroll
                for (int nf = 0; nf < 4; nf++) {
                    int lc = n_base + nf * 8 + 2 * (lane & 3);
                    qp += fmaxf(C[mf][nf][half * 2 + 0] + sb2[lc], 0.f) * sw3[lc];
                    qp += fmaxf(C[mf][nf][half * 2 + 1] + sb2[lc + 1], 0.f) * sw3[lc + 1];
                }
                qp += __shfl_xor_sync(0xffffffffu, qp, 1);
                qp += __shfl_xor_sync(0xffffffffu, qp, 2);
                if ((lane & 3) == 0 && sidx[r] == g) atomicAdd(out + b0 + r, qp);
            }
        __syncthreads();
    }
}

extern "C" void kernel_launch(void* const* d_in, const int* in_sizes, int n_in,
                              void* d_out, int out_size) {
    const float* state  = (const float*)d_in[0];
    const float* action = (const float*)d_in[1];
    const int*   idx    = (const int*)d_in[2];
    const float* W1     = (const float*)d_in[3];
    const float* b1     = (const float*)d_in[4];
    const float* W2s    = (const float*)d_in[5];
    const float* b2s    = (const float*)d_in[6];
    const float* W2a    = (const float*)d_in[7];
    const float* W3     = (const float*)d_in[8];
    const float* b3     = (const float*)d_in[9];
    float* out = (float*)d_out;

    cudaFuncSetAttribute(h1_mma_kernel,  cudaFuncAttributeMaxDynamicSharedMemorySize, SM1_BYTES);
    cudaFuncSetAttribute(h2q_mma_kernel, cudaFuncAttributeMaxDynamicSharedMemorySize, SM2_BYTES);

    init_out_kernel<<<(B_TOT + 255) / 256, 256>>>(idx, b3, out);
    fill_pad_kernel<<<(B_TOT + 255) / 256, 256>>>(action);
    h1_mma_kernel<<<dim3(10, B_TOT / 128), 256, SM1_BYTES>>>(state, idx, W1, b1);
    h2q_mma_kernel<<<dim3(8, B_TOT / 128), 256, SM2_BYTES>>>(idx, W2s, b2s, W2a, W3, out);
}

// round 4
// speedup vs baseline: 3.7345x; 1.1555x over previous
#include <cuda_runtime.h>
#include <cuda_bf16.h>
#include <cstdint>
#include <cstddef>

#define B_TOT 32768
#define D_IN  128
#define A_DIM 16
#define H1D   600
#define H2D   500
#define KP    640   // padded K for gemm2
#define G_N   8

#define CK     64      // K-chunk (cols) per stage
#define ROWB   144u    // smem bytes per row (64 bf16 + 8 pad) - conflict-free ldmatrix
#define A_HALF 18432u  // 128 rows * 144B
#define B_HALF 9216u   // 64 rows * 144B
#define STAGE_BYTES (2u*A_HALF + 2u*B_HALF)  // 55296
#define SMEM_BYTES  (2*STAGE_BYTES + 1024)   // + sb/sw3/sidx tail

// ---- persistent device scratch (pre-split bf16 hi/lo operands) ----
__device__ __nv_bfloat16 g_h1hi[(size_t)B_TOT * KP];
__device__ __nv_bfloat16 g_h1lo[(size_t)B_TOT * KP];
__device__ __nv_bfloat16 g_Sh[(size_t)B_TOT * D_IN];
__device__ __nv_bfloat16 g_Sl[(size_t)B_TOT * D_IN];
__device__ __nv_bfloat16 g_W1h[(size_t)G_N * 640 * D_IN];
__device__ __nv_bfloat16 g_W1l[(size_t)G_N * 640 * D_IN];
__device__ __nv_bfloat16 g_W2h[(size_t)512 * 576];
__device__ __nv_bfloat16 g_W2l[(size_t)512 * 576];
__device__ __nv_bfloat16 g_Bth[(size_t)G_N * 512 * 64];
__device__ __nv_bfloat16 g_Btl[(size_t)G_N * 512 * 64];

// ---------------- helpers ----------------
__device__ __forceinline__ uint32_t smem_u32(const void* p) {
    uint32_t a;
    asm("{ .reg .u64 t; cvta.to.shared.u64 t, %1; cvt.u32.u64 %0, t; }" : "=r"(a) : "l"(p));
    return a;
}
__device__ __forceinline__ void ldm_x4(uint32_t* r, uint32_t addr) {
    asm volatile("ldmatrix.sync.aligned.m8n8.x4.shared.b16 {%0,%1,%2,%3}, [%4];"
                 : "=r"(r[0]), "=r"(r[1]), "=r"(r[2]), "=r"(r[3]) : "r"(addr));
}
__device__ __forceinline__ void mma16816(float* c, const uint32_t* a, const uint32_t* b) {
    asm volatile("mma.sync.aligned.m16n8k16.row.col.f32.bf16.bf16.f32 "
                 "{%0,%1,%2,%3}, {%4,%5,%6,%7}, {%8,%9}, {%0,%1,%2,%3};"
                 : "+f"(c[0]), "+f"(c[1]), "+f"(c[2]), "+f"(c[3])
                 : "r"(a[0]), "r"(a[1]), "r"(a[2]), "r"(a[3]), "r"(b[0]), "r"(b[1]));
}
__device__ __forceinline__ void cp16(uint32_t dst, const void* src) {
    asm volatile("cp.async.cg.shared.global [%0], [%1], 16;" :: "r"(dst), "l"(src) : "memory");
}
__device__ __forceinline__ void cp_commit() { asm volatile("cp.async.commit_group;" ::: "memory"); }
template<int N> __device__ __forceinline__ void cp_wait() {
    asm volatile("cp.async.wait_group %0;" :: "n"(N) : "memory");
}

__device__ __forceinline__ uint32_t pack2(float f0, float f1) {
    uint32_t r;
    asm("cvt.rn.bf16x2.f32 %0, %1, %2;" : "=r"(r) : "f"(f1), "f"(f0));
    return r;
}
__device__ __forceinline__ void split2(float f0, float f1, uint32_t& h, uint32_t& l) {
    h = pack2(f0, f1);
    float h0 = __uint_as_float(h << 16);
    float h1 = __uint_as_float(h & 0xffff0000u);
    l = pack2(f0 - h0, f1 - h1);
}
__device__ __forceinline__ void split8(float4 v0, float4 v1, uint4& H, uint4& L) {
    split2(v0.x, v0.y, H.x, L.x);
    split2(v0.z, v0.w, H.y, L.y);
    split2(v1.x, v1.y, H.z, L.z);
    split2(v1.z, v1.w, H.w, L.w);
}

// ---------------- prep kernels ----------------
__global__ __launch_bounds__(256) void init_out_kernel(const int* __restrict__ idx,
                                                       const float* __restrict__ b3,
                                                       float* __restrict__ out) {
    int i = blockIdx.x * 256 + threadIdx.x;
    if (i < B_TOT) out[i] = b3[idx[i]];
}

// g_h1 cols 600..615 = action hi/lo, 616..639 = 0
__global__ __launch_bounds__(256) void fill_pad_kernel(const float* __restrict__ action) {
    int b = blockIdx.x * 256 + threadIdx.x;
    if (b >= B_TOT) return;
    const float4* a4 = (const float4*)(action + (size_t)b * A_DIM);
    uint4 H0, L0, H1, L1;
    split8(a4[0], a4[1], H0, L0);
    split8(a4[2], a4[3], H1, L1);
    uint16_t* ph = (uint16_t*)g_h1hi + (size_t)b * KP + 600;
    uint16_t* pl = (uint16_t*)g_h1lo + (size_t)b * KP + 600;
    ((uint4*)ph)[0] = H0; ((uint4*)ph)[1] = H1;
    ((uint4*)pl)[0] = L0; ((uint4*)pl)[1] = L1;
    uint4 z = make_uint4(0, 0, 0, 0);
    ((uint4*)(ph + 16))[0] = z; ((uint4*)(ph + 16))[1] = z; ((uint4*)(ph + 16))[2] = z;
    ((uint4*)(pl + 16))[0] = z; ((uint4*)(pl + 16))[1] = z; ((uint4*)(pl + 16))[2] = z;
}

__global__ __launch_bounds__(256) void split_state_kernel(const float* __restrict__ state) {
    size_t e = ((size_t)blockIdx.x * 256 + threadIdx.x) * 8;
    if (e >= (size_t)B_TOT * D_IN) return;
    const float4* s4 = (const float4*)(state + e);
    uint4 H, L;
    split8(s4[0], s4[1], H, L);
    *(uint4*)((uint16_t*)g_Sh + e) = H;
    *(uint4*)((uint16_t*)g_Sl + e) = L;
}

__global__ __launch_bounds__(256) void split_W1_kernel(const float* __restrict__ W1) {
    size_t e = ((size_t)blockIdx.x * 256 + threadIdx.x) * 8;
    if (e >= (size_t)G_N * 640 * D_IN) return;
    int g = (int)(e / (640 * D_IN));
    int r = (int)((e / D_IN) % 640);
    int c = (int)(e % D_IN);
    uint4 H = make_uint4(0, 0, 0, 0), L = H;
    if (r < H1D) {
        const float4* s4 = (const float4*)(W1 + ((size_t)g * H1D + r) * D_IN + c);
        split8(s4[0], s4[1], H, L);
    }
    *(uint4*)((uint16_t*)g_W1h + e) = H;
    *(uint4*)((uint16_t*)g_W1l + e) = L;
}

__global__ __launch_bounds__(256) void split_W2_kernel(const float* __restrict__ W2s) {
    size_t e = ((size_t)blockIdx.x * 256 + threadIdx.x) * 8;
    if (e >= (size_t)512 * 576) return;
    int n = (int)(e / 576);
    int c = (int)(e % 576);
    uint4 H = make_uint4(0, 0, 0, 0), L = H;
    if (n < H2D) {
        const float4* s4 = (const float4*)(W2s + (size_t)n * H1D + c);
        split8(s4[0], s4[1], H, L);
    }
    *(uint4*)((uint16_t*)g_W2h + e) = H;
    *(uint4*)((uint16_t*)g_W2l + e) = L;
}

// Btail[g][n][0..63] = cols 576..639 of [W2s | W2a[g] | 0]
__global__ __launch_bounds__(256) void split_Bt_kernel(const float* __restrict__ W2s,
                                                       const float* __restrict__ W2a) {
    size_t e = ((size_t)blockIdx.x * 256 + threadIdx.x) * 8;
    if (e >= (size_t)G_N * 512 * 64) return;
    int g = (int)(e / (512 * 64));
    int n = (int)((e / 64) % 512);
    int cc = (int)(e % 64);
    float v[8];
    #pragma unroll
    for (int j = 0; j < 8; j++) {
        int c = cc + j;
        float x = 0.f;
        if (n < H2D) {
            if (c < 24) x = W2s[(size_t)n * H1D + 576 + c];
            else if (c < 40) x = W2a[((size_t)g * H2D + n) * A_DIM + (c - 24)];
        }
        v[j] = x;
    }
    uint4 H, L;
    split8(make_float4(v[0], v[1], v[2], v[3]), make_float4(v[4], v[5], v[6], v[7]), H, L);
    *(uint4*)((uint16_t*)g_Bth + e) = H;
    *(uint4*)((uint16_t*)g_Btl + e) = L;
}

// ---------------- GEMM kernels ----------------
// shared mma body: stage at byte offset s*STAGE_BYTES: [Ah|Al|Bh|Bl]
#define MMA_STAGE(sbase, s)                                                        \
    {                                                                              \
        const uint32_t SA = (sbase) + (uint32_t)(s) * STAGE_BYTES;                 \
        const uint32_t SAh = SA, SAl = SA + A_HALF;                                \
        const uint32_t SBh = SA + 2u * A_HALF, SBl = SBh + B_HALF;                 \
        _Pragma("unroll")                                                          \
        for (int kk = 0; kk < 4; kk++) {                                           \
            uint32_t ah[2][4], al[2][4], bh[4][2], bl[4][2];                       \
            _Pragma("unroll")                                                      \
            for (int mf = 0; mf < 2; mf++) {                                       \
                ldm_x4(ah[mf], SAh + aoff + mf * 2304u + kk * 32u);                \
                ldm_x4(al[mf], SAl + aoff + mf * 2304u + kk * 32u);                \
            }                                                                      \
            _Pragma("unroll")                                                      \
            for (int nq = 0; nq < 2; nq++) {                                       \
                uint32_t t[4];                                                     \
                ldm_x4(t, SBh + boff + nq * 2304u + kk * 32u);                     \
                bh[nq * 2][0] = t[0]; bh[nq * 2][1] = t[2];                        \
                bh[nq * 2 + 1][0] = t[1]; bh[nq * 2 + 1][1] = t[3];                \
                ldm_x4(t, SBl + boff + nq * 2304u + kk * 32u);                     \
                bl[nq * 2][0] = t[0]; bl[nq * 2][1] = t[2];                        \
                bl[nq * 2 + 1][0] = t[1]; bl[nq * 2 + 1][1] = t[3];                \
            }                                                                      \
            _Pragma("unroll")                                                      \
            for (int mf = 0; mf < 2; mf++)                                         \
                _Pragma("unroll")                                                  \
                for (int nf = 0; nf < 4; nf++) {                                   \
                    mma16816(C[mf][nf], ah[mf], bh[nf]);                           \
                    mma16816(C[mf][nf], ah[mf], bl[nf]);                           \
                    mma16816(C[mf][nf], al[mf], bh[nf]);                           \
                }                                                                  \
        }                                                                          \
    }

// GEMM1: h1 = relu(state . W1[g]^T + b1[g]) -> g_h1 hi/lo. M=128,N=64,K=128 (2 chunks)
__global__ __launch_bounds__(256, 2) void h1_mma_kernel(const int* __restrict__ idx,
                                                        const float* __restrict__ b1) {
    extern __shared__ char dsm[];
    const uint32_t sbase = smem_u32(dsm);
    float* sb1 = (float*)(dsm + 2 * STAGE_BYTES);
    int* sidx = (int*)(sb1 + 64);
    const int tid = threadIdx.x, lane = tid & 31, wid = tid >> 5;
    const int n0 = blockIdx.x * 64, b0 = blockIdx.y * 128;
    if (tid < 128) sidx[tid] = idx[b0 + tid];
    __syncthreads();
    const int g_lo = sidx[0], g_hi = sidx[127];
    const int m_base = (wid >> 1) * 32, n_base = (wid & 1) * 32;
    const uint32_t aoff = (uint32_t)(m_base + (lane & 15)) * ROWB + (uint32_t)((lane >> 4) * 16);
    const uint32_t boff = (uint32_t)(n_base + (lane & 15)) * ROWB + (uint32_t)((lane >> 4) * 16);

    for (int g = g_lo; g <= g_hi; ++g) {
        if (tid < 64) { int n = n0 + tid; sb1[tid] = (n < H1D) ? b1[(size_t)g * H1D + n] : 0.f; }
        // issue chunk kc into stage s
        auto issue = [&](int kc, int s) {
            #pragma unroll
            for (int i = 0; i < 8; i++) {
                int bid = tid + i * 256;
                int arr = bid >> 10, rem = bid & 1023;
                int row = rem >> 3, q = rem & 7;
                const __nv_bfloat16* src = (arr ? g_Sl : g_Sh) + (size_t)(b0 + row) * D_IN + kc * CK + q * 8;
                cp16(sbase + (uint32_t)s * STAGE_BYTES + (uint32_t)arr * A_HALF + row * ROWB + q * 16u, src);
            }
            #pragma unroll
            for (int i = 0; i < 4; i++) {
                int bid = tid + i * 256;
                int arr = bid >> 9, rem = bid & 511;
                int row = rem >> 3, q = rem & 7;
                const __nv_bfloat16* src = (arr ? g_W1l : g_W1h) + ((size_t)g * 640 + n0 + row) * D_IN + kc * CK + q * 8;
                cp16(sbase + (uint32_t)s * STAGE_BYTES + 2u * A_HALF + (uint32_t)arr * B_HALF + row * ROWB + q * 16u, src);
            }
            cp_commit();
        };
        issue(0, 0);
        float C[2][4][4];
        #pragma unroll
        for (int mf = 0; mf < 2; mf++)
            #pragma unroll
            for (int nf = 0; nf < 4; nf++)
                #pragma unroll
                for (int e = 0; e < 4; e++) C[mf][nf][e] = 0.f;

        issue(1, 1);
        cp_wait<1>();
        __syncthreads();
        MMA_STAGE(sbase, 0);
        cp_wait<0>();
        __syncthreads();
        MMA_STAGE(sbase, 1);

        // epilogue: +b1, relu, split, store rows owned by g
        #pragma unroll
        for (int mf = 0; mf < 2; mf++)
            #pragma unroll
            for (int half = 0; half < 2; half++) {
                int r = m_base + mf * 16 + (lane >> 2) + half * 8;
                if (sidx[r] == g) {
                    size_t base = (size_t)(b0 + r) * KP;
                    #pragma unroll
                    for (int nf = 0; nf < 4; nf++) {
                        int lc = n_base + nf * 8 + 2 * (lane & 3);
                        int n = n0 + lc;
                        if (n < H1D) {
                            float v0 = fmaxf(C[mf][nf][half * 2 + 0] + sb1[lc], 0.f);
                            float v1 = fmaxf(C[mf][nf][half * 2 + 1] + sb1[lc + 1], 0.f);
                            uint32_t h, l;
                            split2(v0, v1, h, l);
                            *(uint32_t*)(g_h1hi + base + n) = h;
                            *(uint32_t*)(g_h1lo + base + n) = l;
                        }
                    }
                }
            }
        __syncthreads();
    }
}

// GEMM2 fused: q += relu([h1|act|0].[W2s|W2a[g]|0]^T + b2s) . W3[g]. M=128,N=64,K=640 (10 chunks)
__global__ __launch_bounds__(256, 2) void h2q_mma_kernel(const int* __restrict__ idx,
                                                         const float* __restrict__ b2s,
                                                         const float* __restrict__ W3,
                                                         float* __restrict__ out) {
    extern __shared__ char dsm[];
    const uint32_t sbase = smem_u32(dsm);
    float* sb2 = (float*)(dsm + 2 * STAGE_BYTES);
    float* sw3 = sb2 + 64;
    int* sidx = (int*)(sw3 + 64);
    const int tid = threadIdx.x, lane = tid & 31, wid = tid >> 5;
    const int n0 = blockIdx.x * 64, b0 = blockIdx.y * 128;
    if (tid < 128) sidx[tid] = idx[b0 + tid];
    if (tid < 64) { int n = n0 + tid; sb2[tid] = (n < H2D) ? b2s[n] : 0.f; }
    __syncthreads();
    const int g_lo = sidx[0], g_hi = sidx[127];
    const int m_base = (wid >> 1) * 32, n_base = (wid & 1) * 32;
    const uint32_t aoff = (uint32_t)(m_base + (lane & 15)) * ROWB + (uint32_t)((lane >> 4) * 16);
    const uint32_t boff = (uint32_t)(n_base + (lane & 15)) * ROWB + (uint32_t)((lane >> 4) * 16);

    for (int g = g_lo; g <= g_hi; ++g) {
        if (tid < 64) { int n = n0 + tid; sw3[tid] = (n < H2D) ? W3[(size_t)g * H2D + n] : 0.f; }
        auto issue = [&](int kc, int s) {
            #pragma unroll
            for (int i = 0; i < 8; i++) {
                int bid = tid + i * 256;
                int arr = bid >> 10, rem = bid & 1023;
                int row = rem >> 3, q = rem & 7;
                const __nv_bfloat16* src = (arr ? g_h1lo : g_h1hi) + (size_t)(b0 + row) * KP + kc * CK + q * 8;
                cp16(sbase + (uint32_t)s * STAGE_BYTES + (uint32_t)arr * A_HALF + row * ROWB + q * 16u, src);
            }
            #pragma unroll
            for (int i = 0; i < 4; i++) {
                int bid = tid + i * 256;
                int arr = bid >> 9, rem = bid & 511;
                int row = rem >> 3, q = rem & 7;
                const __nv_bfloat16* src;
                if (kc < 9)
                    src = (arr ? g_W2l : g_W2h) + (size_t)(n0 + row) * 576 + kc * CK + q * 8;
                else
                    src = (arr ? g_Btl : g_Bth) + ((size_t)g * 512 + n0 + row) * 64 + q * 8;
                cp16(sbase + (uint32_t)s * STAGE_BYTES + 2u * A_HALF + (uint32_t)arr * B_HALF + row * ROWB + q * 16u, src);
            }
            cp_commit();
        };

        float C[2][4][4];
        #pragma unroll
        for (int mf = 0; mf < 2; mf++)
            #pragma unroll
            for (int nf = 0; nf < 4; nf++)
                #pragma unroll
                for (int e = 0; e < 4; e++) C[mf][nf][e] = 0.f;

        issue(0, 0);
        for (int kc = 0; kc < 10; ++kc) {
            if (kc < 9) { issue(kc + 1, (kc + 1) & 1); cp_wait<1>(); }
            else        { cp_wait<0>(); }
            __syncthreads();
            MMA_STAGE(sbase, kc & 1);
            __syncthreads();
        }

        // epilogue: relu(+b2s) . W3, quad-reduce, atomicAdd
        #pragma unroll
        for (int mf = 0; mf < 2; mf++)
            #pragma unroll
            for (int half = 0; half < 2; half++) {
                int r = m_base + mf * 16 + (lane >> 2) + half * 8;
                float qp = 0.f;
                #pragma unroll
                for (int nf = 0; nf < 4; nf++) {
                    int lc = n_base + nf * 8 + 2 * (lane & 3);
                    qp += fmaxf(C[mf][nf][half * 2 + 0] + sb2[lc], 0.f) * sw3[lc];
                    qp += fmaxf(C[mf][nf][half * 2 + 1] + sb2[lc + 1], 0.f) * sw3[lc + 1];
                }
                qp += __shfl_xor_sync(0xffffffffu, qp, 1);
                qp += __shfl_xor_sync(0xffffffffu, qp, 2);
                if ((lane & 3) == 0 && sidx[r] == g) atomicAdd(out + b0 + r, qp);
            }
        __syncthreads();
    }
}

extern "C" void kernel_launch(void* const* d_in, const int* in_sizes, int n_in,
                              void* d_out, int out_size) {
    const float* state  = (const float*)d_in[0];
    const float* action = (const float*)d_in[1];
    const int*   idx    = (const int*)d_in[2];
    const float* W1     = (const float*)d_in[3];
    const float* b1     = (const float*)d_in[4];
    const float* W2s    = (const float*)d_in[5];
    const float* b2s    = (const float*)d_in[6];
    const float* W2a    = (const float*)d_in[7];
    const float* W3     = (const float*)d_in[8];
    const float* b3     = (const float*)d_in[9];
    float* out = (float*)d_out;

    cudaFuncSetAttribute(h1_mma_kernel,  cudaFuncAttributeMaxDynamicSharedMemorySize, SMEM_BYTES);
    cudaFuncSetAttribute(h2q_mma_kernel, cudaFuncAttributeMaxDynamicSharedMemorySize, SMEM_BYTES);

    init_out_kernel<<<(B_TOT + 255) / 256, 256>>>(idx, b3, out);
    fill_pad_kernel<<<(B_TOT + 255) / 256, 256>>>(action);
    split_state_kernel<<<(B_TOT * D_IN / 8 + 255) / 256, 256>>>(state);
    split_W1_kernel<<<(G_N * 640 * D_IN / 8 + 255) / 256, 256>>>(W1);
    split_W2_kernel<<<(512 * 576 / 8 + 255) / 256, 256>>>(W2s);
    split_Bt_kernel<<<(G_N * 512 * 64 / 8 + 255) / 256, 256>>>(W2s, W2a);
    h1_mma_kernel<<<dim3(10, B_TOT / 128), 256, SMEM_BYTES>>>(idx, b1);
    h2q_mma_kernel<<<dim3(8, B_TOT / 128), 256, SMEM_BYTES>>>(idx, b2s, W3, out);
}